// round 4
// baseline (speedup 1.0000x reference)
#include <cuda_runtime.h>
#include <cstdint>
#include <cstddef>

// ---------------- problem geometry ----------------
#define IN_W   512
#define IN_H   512
#define OUT_W  1024
#define OUT_H  1024
#define NB     32
#define NC     3

// output tile per CTA
#define TX     128
#define TY     32
// input tile (with 8-tap halo): rows = TY/2 + 8 = 24, cols = TX/2 + 8 = 72
#define ITR    24
#define ITC    72

// ---------------- compile-time Lanczos4 weights (2 phases) ----------------
// scale = 0.5 exactly => fractional phases are 0.75 (even outputs) and 0.25 (odd).
struct W16 { float w0[8]; float w1[8]; };

constexpr W16 make_weights() {
    const double sq  = 0.70710678118654752440;   // |sin(pi*d)|
    const double s1  = 0.19509032201612826785;   // sin(pi/16)
    const double s3  = 0.55557023301960222474;   // sin(3pi/16)
    const double s5  = 0.83146961230254523708;   // sin(5pi/16)
    const double s7  = 0.98078528040323044913;   // sin(7pi/16)
    const double pi  = 3.14159265358979323846;
    const double d[8]    = { 3.75,  2.75,  1.75,  0.75, -0.25, -1.25, -2.25, -3.25 };
    const double spd[8]  = { -sq ,  sq  , -sq  ,  sq  , -sq  ,  sq  , -sq  ,  sq   };
    const double spd4[8] = {  s1 ,  s5  ,  s7  ,  s3  , -s1  , -s5  , -s7  , -s3   };
    double raw[8] = {};
    double s = 0.0;
    for (int t = 0; t < 8; ++t) {
        raw[t] = spd[t] * spd4[t] * 4.0 / (pi * pi * d[t] * d[t]);
        s += raw[t];
    }
    W16 r{};
    for (int t = 0; t < 8; ++t) {
        r.w0[t]     = (float)(raw[t] / s);  // phase 0.75 (even output index)
        r.w1[7 - t] = (float)(raw[t] / s);  // phase 0.25 = mirror
    }
    return r;
}
constexpr W16 KW = make_weights();

// ---------------- per-image min/max scratch ----------------
__device__ unsigned g_minenc[NB];
__device__ unsigned g_maxenc[NB];

__device__ __forceinline__ unsigned encf(float f) {
    unsigned u = __float_as_uint(f);
    return (u & 0x80000000u) ? ~u : (u | 0x80000000u);
}
__device__ __forceinline__ float decf(unsigned e) {
    return (e & 0x80000000u) ? __uint_as_float(e & 0x7FFFFFFFu) : __uint_as_float(~e);
}

__global__ void k_init_minmax() {
    unsigned i = threadIdx.x;
    if (i < NB) { g_minenc[i] = 0xFFFFFFFFu; g_maxenc[i] = 0u; }
}

// StableHLO-style saturating f32 -> u8 convert:
// negatives/NaN -> 0, > 255 -> 255, otherwise trunc toward zero.
__device__ __forceinline__ float cast_u8f(float y) {
    unsigned u = __float2uint_rz(y);     // saturates negatives & NaN to 0
    return (float)(u > 255u ? 255u : u); // saturate high
}

__device__ __forceinline__ float renorm_u8f(float im, bool ren, float s1f, float s2f) {
    const float ott = 1.0f / 255.0f;
    const float ubt = -10.0f / 255.0f;
    float v1 = (im > 1.0f) ? fmaf(im - 1.0f, s1f, 1.0f - ott)
             : ((im < 1.0f) ? im * (1.0f - ott) : im);
    float v2 = (v1 < 0.0f) ? fmaf(v1, s2f, ubt)
             : ((v1 > 0.0f) ? v1 * (1.0f - ubt) : v1);
    float y = (ren ? v2 : im) * 255.0f;
    return cast_u8f(y);
}

// PASS 0: resize tile, reduce per-image min/max (no stores).
// PASS 1: resize tile, renormalize, store float32 (uint8-valued).
template <int PASS>
__global__ void __launch_bounds__(256, 4)
k_resize(const float* __restrict__ x, float* __restrict__ out)
{
    const int bc  = blockIdx.z;          // b*3 + c
    const int img = bc / 3;              // image index b (min/max over C,H,W)
    const int ox0 = blockIdx.x * TX;
    const int oy0 = blockIdx.y * TY;
    const int ix0 = (ox0 >> 1) - 4;
    const int iy0 = (oy0 >> 1) - 4;
    const float* __restrict__ src = x + (size_t)bc * (IN_W * IN_H);

    __shared__ float s_in[ITR * ITC];    // replicate-padded input tile
    __shared__ float s_it[TY * ITC];     // H-resampled intermediate

    const int tid = threadIdx.x;

    const float w0[8] = { KW.w0[0], KW.w0[1], KW.w0[2], KW.w0[3],
                          KW.w0[4], KW.w0[5], KW.w0[6], KW.w0[7] };
    const float w1[8] = { KW.w1[0], KW.w1[1], KW.w1[2], KW.w1[3],
                          KW.w1[4], KW.w1[5], KW.w1[6], KW.w1[7] };

    // ---- load input tile (replicate border via clamped global index) ----
    for (int e = tid; e < ITR * ITC; e += 256) {
        int r = e / ITC;
        int c = e - r * ITC;
        int gy = iy0 + r;  gy = gy < 0 ? 0 : (gy > IN_H - 1 ? IN_H - 1 : gy);
        int gx = ix0 + c;  gx = gx < 0 ? 0 : (gx > IN_W - 1 ? IN_W - 1 : gx);
        s_in[e] = __ldg(src + gy * IN_W + gx);
    }
    __syncthreads();

    // ---- H resample: 12-row register window -> 8 output rows per unit ----
    for (int u = tid; u < ITC * 4; u += 256) {
        int c  = u % ITC;
        int rg = u / ITC;
        float v[12];
#pragma unroll
        for (int k = 0; k < 12; ++k)
            v[k] = s_in[(rg * 4 + k) * ITC + c];
#pragma unroll
        for (int j = 0; j < 8; ++j) {
            const int off = (j + (j & 1)) >> 1;     // even j: j/2 ; odd j: (j+1)/2
            float acc = 0.0f;
#pragma unroll
            for (int t = 0; t < 8; ++t)
                acc = fmaf((j & 1) ? w1[t] : w0[t], v[off + t], acc);
            s_it[(rg * 8 + j) * ITC + c] = acc;
        }
    }
    __syncthreads();

    // ---- W resample: 10-float window -> 4 output cols per thread-row ----
    float lmin =  3.0e38f, lmax = -3.0e38f;
    float s1f = 0.0f, s2f = 0.0f;
    bool  ren = false;
    if (PASS == 1) {
        float mn = decf(g_minenc[img]);
        float mx = decf(g_maxenc[img]);
        ren = (mx - mn) > 1.0f;
        float otr = mx - 1.0f;
        s1f = (1.0f / 255.0f)   / (otr != 0.0f ? otr : 1.0f);
        s2f = (-10.0f / 255.0f) / (mn  != 0.0f ? mn  : 1.0f);
    }

    const int g  = tid & 31;     // column group: output cols [4g, 4g+3]
    const int r0 = tid >> 5;     // warp id = starting row
#pragma unroll
    for (int it = 0; it < 4; ++it) {
        const int r = r0 + it * 8;
        const float2* p2 = reinterpret_cast<const float2*>(&s_it[r * ITC + 2 * g]);
        float2 a0 = p2[0], a1 = p2[1], a2 = p2[2], a3 = p2[3], a4 = p2[4];
        float v[10] = { a0.x, a0.y, a1.x, a1.y, a2.x, a2.y, a3.x, a3.y, a4.x, a4.y };

        float o0 = 0.0f, o1 = 0.0f, o2 = 0.0f, o3 = 0.0f;
#pragma unroll
        for (int t = 0; t < 8; ++t) {
            o0 = fmaf(w0[t], v[t],     o0);   // col 4g   (even phase)
            o1 = fmaf(w1[t], v[t + 1], o1);   // col 4g+1 (odd phase)
            o2 = fmaf(w0[t], v[t + 1], o2);   // col 4g+2 (even phase)
            o3 = fmaf(w1[t], v[t + 2], o3);   // col 4g+3 (odd phase)
        }

        if (PASS == 0) {
            lmin = fminf(lmin, fminf(fminf(o0, o1), fminf(o2, o3)));
            lmax = fmaxf(lmax, fmaxf(fmaxf(o0, o1), fmaxf(o2, o3)));
        } else {
            float4 q;
            q.x = renorm_u8f(o0, ren, s1f, s2f);
            q.y = renorm_u8f(o1, ren, s1f, s2f);
            q.z = renorm_u8f(o2, ren, s1f, s2f);
            q.w = renorm_u8f(o3, ren, s1f, s2f);
            size_t oidx = (size_t)bc * (OUT_H * OUT_W) + (size_t)(oy0 + r) * OUT_W + ox0 + 4 * g;
            *reinterpret_cast<float4*>(out + oidx) = q;
        }
    }

    if (PASS == 0) {
#pragma unroll
        for (int o = 16; o; o >>= 1) {
            lmin = fminf(lmin, __shfl_xor_sync(0xFFFFFFFFu, lmin, o));
            lmax = fmaxf(lmax, __shfl_xor_sync(0xFFFFFFFFu, lmax, o));
        }
        __shared__ float red[16];
        const int wid = tid >> 5;
        if ((tid & 31) == 0) { red[wid] = lmin; red[8 + wid] = lmax; }
        __syncthreads();
        if (tid == 0) {
            float m0 = red[0], m1 = red[8];
#pragma unroll
            for (int i = 1; i < 8; ++i) {
                m0 = fminf(m0, red[i]);
                m1 = fmaxf(m1, red[8 + i]);
            }
            atomicMin(&g_minenc[img], encf(m0));
            atomicMax(&g_maxenc[img], encf(m1));
        }
    }
}

extern "C" void kernel_launch(void* const* d_in, const int* in_sizes, int n_in,
                              void* d_out, int out_size) {
    const float* x = (const float*)d_in[0];
    float* out = (float*)d_out;

    dim3 grid(OUT_W / TX, OUT_H / TY, NB * NC);   // 8 x 32 x 96
    k_init_minmax<<<1, 32>>>();
    k_resize<0><<<grid, 256>>>(x, nullptr);       // resize + per-image min/max
    k_resize<1><<<grid, 256>>>(x, out);           // resize + renorm + f32(u8) store
}